// round 5
// baseline (speedup 1.0000x reference)
#include <cuda_runtime.h>
#include <math.h>

// Problem constants (fixed shapes)
#define S_LEN 2048
#define B_SZ  64
#define H_DIM 1024
#define D_HALF 64
#define W_WIN 129            // 2*D+1
#define DCH   64             // d-chunk for GEMM partial
#define NDC   (H_DIM / DCH)  // 16
#define GRID_BLOCKS 128
#define NTHREADS 256

// Scratch (allocation-free)
__device__ float g_dotp[NDC * B_SZ * H_DIM];   // [dc][b][h]  4 MB
__device__ float g_p[B_SZ];
__device__ int   g_center[B_SZ];
__device__ float g_scores[B_SZ * W_WIN];
__device__ float g_attn[B_SZ * W_WIN];

// grid barrier state (zero-initialized at module load; gen is monotonic so
// repeated graph replays are safe and deterministic)
__device__ unsigned          g_bar_count = 0;
__device__ volatile unsigned g_bar_gen   = 0;

__device__ __forceinline__ void grid_barrier() {
    __syncthreads();
    if (threadIdx.x == 0) {
        unsigned gen = g_bar_gen;
        __threadfence();                              // release prior writes
        if (atomicAdd(&g_bar_count, 1u) == GRID_BLOCKS - 1) {
            g_bar_count = 0;                          // reset before open
            __threadfence();
            g_bar_gen = gen + 1;                      // open the gate
        } else {
            while (g_bar_gen == gen) __nanosleep(32);
        }
        __threadfence();                              // acquire
    }
    __syncthreads();
}

// smem: one union reused across phases (33.3 KB max, static -> <48 KB limit)
struct SmemGemm   { float sh_h[64][DCH + 1]; float sh_w[DCH][65]; };
struct SmemScores { float hid[H_DIM]; };
struct SmemSoft   { float red[NTHREADS]; };
struct SmemCtx    { float attn[W_WIN]; float4 ctx[128]; };
union SmemU { SmemGemm g; SmemScores s; SmemSoft r; SmemCtx c; };

// ---------------------------------------------------------------------------
// One persistent kernel, 128 blocks x 256 threads, all co-resident.
// fp32 throughout the p-path on purpose: p feeds round() -> window center.
// ---------------------------------------------------------------------------
__global__ __launch_bounds__(NTHREADS, 1)
void k_persistent(const float* __restrict__ hidden,
                  const float* __restrict__ enc,
                  const float* __restrict__ Wp_w,
                  const float* __restrict__ Wp_b,
                  const float* __restrict__ vp_w,
                  const float* __restrict__ vp_b,
                  float* __restrict__ d_out) {
    __shared__ SmemU u;

    const int tid  = threadIdx.x;
    const int lane = tid & 31;
    const int warp = tid >> 5;

    // ===== phase 1: GEMM partials  dotp[dc][b][h] = sum_d hidden[b][d]*Wp_w[h][d]
    for (int job = blockIdx.x; job < 256; job += GRID_BLOCKS) {
        const int h0 = (job & 15) * 64;
        const int dc = job >> 4;
        const int d0 = dc * DCH;

        for (int idx = tid; idx < 64 * 16; idx += NTHREADS) {
            int b  = idx >> 4;
            int dq = (idx & 15) << 2;
            float4 v = *reinterpret_cast<const float4*>(&hidden[b * H_DIM + d0 + dq]);
            u.g.sh_h[b][dq + 0] = v.x; u.g.sh_h[b][dq + 1] = v.y;
            u.g.sh_h[b][dq + 2] = v.z; u.g.sh_h[b][dq + 3] = v.w;
        }
        for (int idx = tid; idx < 64 * 16; idx += NTHREADS) {
            int h  = idx >> 4;
            int dq = (idx & 15) << 2;
            float4 v = *reinterpret_cast<const float4*>(&Wp_w[(size_t)(h0 + h) * H_DIM + d0 + dq]);
            u.g.sh_w[dq + 0][h] = v.x; u.g.sh_w[dq + 1][h] = v.y;
            u.g.sh_w[dq + 2][h] = v.z; u.g.sh_w[dq + 3][h] = v.w;
        }
        __syncthreads();

        const int hl = lane & 15;
        const int bl = ((lane >> 4) << 2) + (warp << 3);

        float acc[4][4] = {};
#pragma unroll 16
        for (int d = 0; d < DCH; ++d) {
            float wv0 = u.g.sh_w[d][hl];
            float wv1 = u.g.sh_w[d][hl + 16];
            float wv2 = u.g.sh_w[d][hl + 32];
            float wv3 = u.g.sh_w[d][hl + 48];
            float hv0 = u.g.sh_h[bl + 0][d];
            float hv1 = u.g.sh_h[bl + 1][d];
            float hv2 = u.g.sh_h[bl + 2][d];
            float hv3 = u.g.sh_h[bl + 3][d];
            acc[0][0] += hv0 * wv0; acc[0][1] += hv0 * wv1; acc[0][2] += hv0 * wv2; acc[0][3] += hv0 * wv3;
            acc[1][0] += hv1 * wv0; acc[1][1] += hv1 * wv1; acc[1][2] += hv1 * wv2; acc[1][3] += hv1 * wv3;
            acc[2][0] += hv2 * wv0; acc[2][1] += hv2 * wv1; acc[2][2] += hv2 * wv2; acc[2][3] += hv2 * wv3;
            acc[3][0] += hv3 * wv0; acc[3][1] += hv3 * wv1; acc[3][2] += hv3 * wv2; acc[3][3] += hv3 * wv3;
        }

        float* outp = &g_dotp[(size_t)dc * (B_SZ * H_DIM)];
#pragma unroll
        for (int j = 0; j < 4; ++j) {
            int b = bl + j;
#pragma unroll
            for (int i = 0; i < 4; ++i)
                outp[b * H_DIM + h0 + hl + 16 * i] = acc[j][i];
        }
        __syncthreads();   // smem reused next job
    }
    grid_barrier();

    // ===== phase 2: reduce -> tanh -> p, center  (blocks 0..63)
    if (blockIdx.x < B_SZ) {
        const int b = blockIdx.x;
        float local = 0.f;
        for (int h = tid; h < H_DIM; h += NTHREADS) {
            float pa[NDC];
#pragma unroll
            for (int dc = 0; dc < NDC; ++dc)
                pa[dc] = g_dotp[dc * (B_SZ * H_DIM) + b * H_DIM + h];
            float s = Wp_b[h];
#pragma unroll
            for (int dc = 0; dc < NDC; ++dc) s += pa[dc];
            local += vp_w[h] * tanhf(s);
        }
        u.r.red[tid] = local;
        __syncthreads();
        for (int s = 128; s > 0; s >>= 1) {
            if (tid < s) u.r.red[tid] += u.r.red[tid + s];
            __syncthreads();
        }
        if (tid == 0) {
            float tot = u.r.red[0] + vp_b[0];
            float p = (float)S_LEN / (1.f + expf(-tot));
            g_p[b] = p;
            g_center[b] = (int)rintf(p);   // round-half-even == jnp.round
        }
    }
    grid_barrier();

    // ===== phase 3: scores  (block = (b, w-segment), warp per w, MLP=8)
    {
        const int b   = blockIdx.x >> 1;
        const int seg = blockIdx.x & 1;
        for (int i = tid; i < H_DIM; i += NTHREADS)
            u.s.hid[i] = hidden[b * H_DIM + i];
        __syncthreads();
        const int c = g_center[b];
        const int wbeg = seg * 65;
        const int wend = seg ? W_WIN : 65;
        const float4* h4 = reinterpret_cast<const float4*>(u.s.hid);

        for (int w = wbeg + warp; w < wend; w += 8) {
            const int s = c + w - D_HALF;
            float score = 0.f;
            if (s >= 0 && s < S_LEN) {
                const float4* e4 = reinterpret_cast<const float4*>(
                    enc + ((size_t)s * B_SZ + b) * H_DIM);
                float4 e[8];
#pragma unroll
                for (int k = 0; k < 8; ++k) e[k] = e4[k * 32 + lane];  // batched LDG.128
                float a0 = 0.f, a1 = 0.f, a2 = 0.f, a3 = 0.f;
#pragma unroll
                for (int k = 0; k < 8; ++k) {
                    float4 hh = h4[k * 32 + lane];
                    a0 += e[k].x * hh.x; a1 += e[k].y * hh.y;
                    a2 += e[k].z * hh.z; a3 += e[k].w * hh.w;
                }
                float v = (a0 + a1) + (a2 + a3);
#pragma unroll
                for (int off = 16; off > 0; off >>= 1)
                    v += __shfl_down_sync(0xffffffffu, v, off);
                score = v;
            }
            if (lane == 0) g_scores[b * W_WIN + w] = score;
        }
    }
    grid_barrier();

    // ===== phase 4: softmax x gaussian  (blocks 0..63)
    if (blockIdx.x < B_SZ) {
        const int b = blockIdx.x;
        float sc = (tid < W_WIN) ? g_scores[b * W_WIN + tid] : -1e30f;
        u.r.red[tid] = sc;
        __syncthreads();
        for (int s2 = 128; s2 > 0; s2 >>= 1) {
            if (tid < s2) u.r.red[tid] = fmaxf(u.r.red[tid], u.r.red[tid + s2]);
            __syncthreads();
        }
        float mx = u.r.red[0];
        __syncthreads();
        float e = (tid < W_WIN) ? expf(sc - mx) : 0.f;
        u.r.red[tid] = e;
        __syncthreads();
        for (int s2 = 128; s2 > 0; s2 >>= 1) {
            if (tid < s2) u.r.red[tid] += u.r.red[tid + s2];
            __syncthreads();
        }
        float denom = u.r.red[0];
        if (tid < W_WIN) {
            float p    = g_p[b];
            float pos  = (float)(g_center[b] + tid - D_HALF);
            float diff = pos - p;
            float val  = (e / denom) * expf(-diff * diff * (1.f / 2048.f)); // stddev=D/2=32
            d_out[b * W_WIN + tid] = val;
            g_attn[b * W_WIN + tid] = val;
        }
    }
    grid_barrier();

    // ===== phase 5: context  (block = (b, h-half), 2 w-segments x 128 threads)
    {
        const int b    = blockIdx.x >> 1;
        const int half = blockIdx.x & 1;
        for (int i = tid; i < W_WIN; i += NTHREADS)
            u.c.attn[i] = g_attn[b * W_WIN + i];
        __syncthreads();
        const int c  = g_center[b];
        const int lo = max(0, D_HALF - c);
        const int hi = min(W_WIN, S_LEN + D_HALF - c);
        const int seg  = tid >> 7;     // 0 or 1
        const int hidx = tid & 127;    // float4 index within 512-float half

        const float4* base = reinterpret_cast<const float4*>(
            enc + (size_t)b * H_DIM + half * 512) + hidx;
        const size_t rs4 = (size_t)(B_SZ * H_DIM) / 4;

        float4 acc = make_float4(0.f, 0.f, 0.f, 0.f);
        int w = lo + seg;
        for (; w + 14 < hi; w += 16) {
            float4 ev[8];
            float  av[8];
#pragma unroll
            for (int j = 0; j < 8; ++j) {
                int ww = w + 2 * j;
                ev[j] = base[(size_t)(c + ww - D_HALF) * rs4];   // batched LDG.128
                av[j] = u.c.attn[ww];
            }
#pragma unroll
            for (int j = 0; j < 8; ++j) {
                acc.x += av[j] * ev[j].x; acc.y += av[j] * ev[j].y;
                acc.z += av[j] * ev[j].z; acc.w += av[j] * ev[j].w;
            }
        }
        for (; w < hi; w += 2) {
            float4 ev = base[(size_t)(c + w - D_HALF) * rs4];
            float  a  = u.c.attn[w];
            acc.x += a * ev.x; acc.y += a * ev.y;
            acc.z += a * ev.z; acc.w += a * ev.w;
        }

        if (seg == 1) u.c.ctx[hidx] = acc;
        __syncthreads();
        if (seg == 0) {
            float4 o = u.c.ctx[hidx];
            o.x += acc.x; o.y += acc.y; o.z += acc.z; o.w += acc.w;
            reinterpret_cast<float4*>(
                d_out + B_SZ * W_WIN + b * H_DIM + half * 512)[hidx] = o;
        }
    }
}

// ---------------------------------------------------------------------------
extern "C" void kernel_launch(void* const* d_in, const int* in_sizes, int n_in,
                              void* d_out, int out_size) {
    // metadata order: t, hidden, encoder_outputs, Wp_w, Wp_b, vp_w, vp_b
    const float* hidden = (const float*)d_in[1];
    const float* enc    = (const float*)d_in[2];
    const float* Wp_w   = (const float*)d_in[3];
    const float* Wp_b   = (const float*)d_in[4];
    const float* vp_w   = (const float*)d_in[5];
    const float* vp_b   = (const float*)d_in[6];
    float* out = (float*)d_out;

    k_persistent<<<GRID_BLOCKS, NTHREADS>>>(hidden, enc, Wp_w, Wp_b, vp_w, vp_b, out);
}

// round 6
// speedup vs baseline: 1.3224x; 1.3224x over previous
#include <cuda_runtime.h>
#include <math.h>

// Problem constants (fixed shapes)
#define S_LEN 2048
#define B_SZ  64
#define H_DIM 1024
#define D_HALF 64
#define W_WIN 129            // 2*D+1
#define DCH   64             // d-chunk for GEMM partial
#define NDC   (H_DIM / DCH)  // 16
#define NT    768            // fused kernel threads (24 warps)

// Scratch (allocation-free)
__device__ float g_dotp[NDC * B_SZ * H_DIM];   // [dc][b][h]  4 MB

// ---------------------------------------------------------------------------
// K1: partial GEMM  dotp[dc][b][h] = sum_{d in chunk dc} hidden[b][d]*Wp_w[h][d]
// grid (16 h-tiles, 16 d-chunks), 256 threads; at the fp32 FFMA chip floor.
// fp32 on purpose: p feeds round() -> window center; precision is structural.
// ---------------------------------------------------------------------------
__global__ __launch_bounds__(256, 2)
void k_gemm_partial(const float* __restrict__ hidden,
                    const float* __restrict__ Wp_w) {
    const int h0 = blockIdx.x * 64;
    const int dc = blockIdx.y;
    const int d0 = dc * DCH;

    __shared__ float sh_h[64][65];   // [b][d] padded
    __shared__ float sh_w[DCH][65];  // [d][h] padded (transposed)

    const int tid  = threadIdx.x;
    const int lane = tid & 31;
    const int warp = tid >> 5;

    for (int idx = tid; idx < 64 * 16; idx += 256) {
        int b  = idx >> 4;
        int dq = (idx & 15) << 2;
        float4 v = *reinterpret_cast<const float4*>(&hidden[b * H_DIM + d0 + dq]);
        sh_h[b][dq + 0] = v.x; sh_h[b][dq + 1] = v.y;
        sh_h[b][dq + 2] = v.z; sh_h[b][dq + 3] = v.w;
    }
    for (int idx = tid; idx < 64 * 16; idx += 256) {
        int h  = idx >> 4;
        int dq = (idx & 15) << 2;
        float4 v = *reinterpret_cast<const float4*>(&Wp_w[(size_t)(h0 + h) * H_DIM + d0 + dq]);
        sh_w[dq + 0][h] = v.x; sh_w[dq + 1][h] = v.y;
        sh_w[dq + 2][h] = v.z; sh_w[dq + 3][h] = v.w;
    }
    __syncthreads();

    const int hl = lane & 15;
    const int bl = ((lane >> 4) << 2) + (warp << 3);

    float acc[4][4] = {};
#pragma unroll 16
    for (int d = 0; d < DCH; ++d) {
        float wv0 = sh_w[d][hl];
        float wv1 = sh_w[d][hl + 16];
        float wv2 = sh_w[d][hl + 32];
        float wv3 = sh_w[d][hl + 48];
        float hv0 = sh_h[bl + 0][d];
        float hv1 = sh_h[bl + 1][d];
        float hv2 = sh_h[bl + 2][d];
        float hv3 = sh_h[bl + 3][d];
        acc[0][0] += hv0 * wv0; acc[0][1] += hv0 * wv1; acc[0][2] += hv0 * wv2; acc[0][3] += hv0 * wv3;
        acc[1][0] += hv1 * wv0; acc[1][1] += hv1 * wv1; acc[1][2] += hv1 * wv2; acc[1][3] += hv1 * wv3;
        acc[2][0] += hv2 * wv0; acc[2][1] += hv2 * wv1; acc[2][2] += hv2 * wv2; acc[2][3] += hv2 * wv3;
        acc[3][0] += hv3 * wv0; acc[3][1] += hv3 * wv1; acc[3][2] += hv3 * wv2; acc[3][3] += hv3 * wv3;
    }

    float* outp = &g_dotp[(size_t)dc * (B_SZ * H_DIM)];
#pragma unroll
    for (int j = 0; j < 4; ++j) {
        int b = bl + j;
#pragma unroll
        for (int i = 0; i < 4; ++i)
            outp[b * H_DIM + h0 + hl + 16 * i] = acc[j][i];
    }
}

// ---------------------------------------------------------------------------
// K2 (fused): one block per b, 768 threads (24 warps/SM for latency hiding).
// ---------------------------------------------------------------------------
__global__ __launch_bounds__(NT, 1)
void k_attn_fused(const float* __restrict__ hidden,
                  const float* __restrict__ enc,
                  const float* __restrict__ Wp_b,
                  const float* __restrict__ vp_w,
                  const float* __restrict__ vp_b,
                  float* __restrict__ d_out) {
    const int b    = blockIdx.x;
    const int tid  = threadIdx.x;
    const int lane = tid & 31;
    const int warp = tid >> 5;   // 0..23

    __shared__ __align__(16) float sh_hid[H_DIM];
    __shared__ float  s_red[256];
    __shared__ float  s_wred[24];
    __shared__ float  s_attn[W_WIN];     // raw scores, then attn values
    __shared__ float4 s_c1[256];
    __shared__ float4 s_c2[256];
    __shared__ float  s_p;
    __shared__ int    s_c;

    // stage hidden row
    for (int i = tid; i < H_DIM; i += NT) sh_hid[i] = hidden[b * H_DIM + i];

    // ---- phase 1: reduce partials -> tanh -> p, center ----
    float local = 0.f;
    for (int h = tid; h < H_DIM; h += NT) {
        float pa[NDC];
#pragma unroll
        for (int dc = 0; dc < NDC; ++dc)
            pa[dc] = g_dotp[dc * (B_SZ * H_DIM) + b * H_DIM + h];
        float s = Wp_b[h];
#pragma unroll
        for (int dc = 0; dc < NDC; ++dc) s += pa[dc];
        local += vp_w[h] * tanhf(s);
    }
#pragma unroll
    for (int off = 16; off > 0; off >>= 1)
        local += __shfl_down_sync(0xffffffffu, local, off);
    if (lane == 0) s_wred[warp] = local;
    __syncthreads();
    if (warp == 0) {
        float v = (lane < 24) ? s_wred[lane] : 0.f;
#pragma unroll
        for (int off = 16; off > 0; off >>= 1)
            v += __shfl_down_sync(0xffffffffu, v, off);
        if (lane == 0) {
            float tot = v + vp_b[0];
            float p = (float)S_LEN / (1.f + expf(-tot));
            s_p = p;
            s_c = (int)rintf(p);   // round-half-even == jnp.round
        }
    }
    __syncthreads();
    const int   c = s_c;
    const float p = s_p;

    // ---- phase 2: scores, one warp per window position, MLP=8 ----
    const float4* h4 = reinterpret_cast<const float4*>(sh_hid);
    for (int w = warp; w < W_WIN; w += 24) {
        const int s = c + w - D_HALF;
        float score = 0.f;
        if (s >= 0 && s < S_LEN) {
            const float4* e4 = reinterpret_cast<const float4*>(
                enc + ((size_t)s * B_SZ + b) * H_DIM);
            float4 e[8];
#pragma unroll
            for (int k = 0; k < 8; ++k) e[k] = e4[k * 32 + lane];   // batched LDG.128
            float a0 = 0.f, a1 = 0.f, a2 = 0.f, a3 = 0.f;
#pragma unroll
            for (int k = 0; k < 8; ++k) {
                float4 hh = h4[k * 32 + lane];
                a0 += e[k].x * hh.x; a1 += e[k].y * hh.y;
                a2 += e[k].z * hh.z; a3 += e[k].w * hh.w;
            }
            float v = (a0 + a1) + (a2 + a3);
#pragma unroll
            for (int off = 16; off > 0; off >>= 1)
                v += __shfl_down_sync(0xffffffffu, v, off);
            score = v;
        }
        if (lane == 0) s_attn[w] = score;   // raw score for now
    }
    __syncthreads();

    // ---- phase 3: softmax x gaussian ----
    float sc = (tid < W_WIN) ? s_attn[tid] : -1e30f;
    if (tid < 256) s_red[tid] = sc;
    __syncthreads();
    for (int s2 = 128; s2 > 0; s2 >>= 1) {
        if (tid < s2) s_red[tid] = fmaxf(s_red[tid], s_red[tid + s2]);
        __syncthreads();
    }
    float mx = s_red[0];
    __syncthreads();
    float e = (tid < W_WIN) ? expf(sc - mx) : 0.f;
    if (tid < 256) s_red[tid] = e;
    __syncthreads();
    for (int s2 = 128; s2 > 0; s2 >>= 1) {
        if (tid < s2) s_red[tid] += s_red[tid + s2];
        __syncthreads();
    }
    float denom = s_red[0];
    if (tid < W_WIN) {
        float pos  = (float)(c + tid - D_HALF);
        float diff = pos - p;
        float val  = (e / denom) * expf(-diff * diff * (1.f / 2048.f)); // stddev=D/2=32
        d_out[b * W_WIN + tid] = val;
        s_attn[tid] = val;   // overwrite raw score with attn value
    }
    __syncthreads();

    // ---- phase 4: context, 3 w-segments x 256 h-threads, MLP=8 ----
    const int lo = max(0, D_HALF - c);
    const int hi = min(W_WIN, S_LEN + D_HALF - c);
    const int seg  = tid >> 8;     // 0,1,2
    const int hidx = tid & 255;    // float4 index over full H_DIM

    const float4* base = reinterpret_cast<const float4*>(enc + (size_t)b * H_DIM) + hidx;
    const size_t rs4 = (size_t)(B_SZ * H_DIM) / 4;

    float4 acc = make_float4(0.f, 0.f, 0.f, 0.f);
    int w = lo + seg;
    for (; w + 21 < hi; w += 24) {          // 8-deep batch at stride 3
        float4 ev[8];
        float  av[8];
#pragma unroll
        for (int j = 0; j < 8; ++j) {
            int ww = w + 3 * j;
            ev[j] = base[(size_t)(c + ww - D_HALF) * rs4];   // batched LDG.128
            av[j] = s_attn[ww];
        }
#pragma unroll
        for (int j = 0; j < 8; ++j) {
            acc.x += av[j] * ev[j].x; acc.y += av[j] * ev[j].y;
            acc.z += av[j] * ev[j].z; acc.w += av[j] * ev[j].w;
        }
    }
    for (; w < hi; w += 3) {
        float4 ev = base[(size_t)(c + w - D_HALF) * rs4];
        float  a  = s_attn[w];
        acc.x += a * ev.x; acc.y += a * ev.y;
        acc.z += a * ev.z; acc.w += a * ev.w;
    }

    if (seg == 1) s_c1[hidx] = acc;
    if (seg == 2) s_c2[hidx] = acc;
    __syncthreads();
    if (seg == 0) {
        float4 o1 = s_c1[hidx];
        float4 o2 = s_c2[hidx];
        float4 o;
        o.x = acc.x + o1.x + o2.x;
        o.y = acc.y + o1.y + o2.y;
        o.z = acc.z + o1.z + o2.z;
        o.w = acc.w + o1.w + o2.w;
        reinterpret_cast<float4*>(d_out + B_SZ * W_WIN + b * H_DIM)[hidx] = o;
    }
}

// ---------------------------------------------------------------------------
extern "C" void kernel_launch(void* const* d_in, const int* in_sizes, int n_in,
                              void* d_out, int out_size) {
    // metadata order: t, hidden, encoder_outputs, Wp_w, Wp_b, vp_w, vp_b
    const float* hidden = (const float*)d_in[1];
    const float* enc    = (const float*)d_in[2];
    const float* Wp_w   = (const float*)d_in[3];
    const float* Wp_b   = (const float*)d_in[4];
    const float* vp_w   = (const float*)d_in[5];
    const float* vp_b   = (const float*)d_in[6];
    float* out = (float*)d_out;

    k_gemm_partial<<<dim3(16, 16), 256>>>(hidden, Wp_w);
    k_attn_fused<<<B_SZ, NT>>>(hidden, enc, Wp_b, vp_w, vp_b, out);
}

// round 7
// speedup vs baseline: 1.4548x; 1.1001x over previous
#include <cuda_runtime.h>
#include <cooperative_groups.h>
#include <math.h>

namespace cg = cooperative_groups;

// Problem constants (fixed shapes)
#define S_LEN 2048
#define B_SZ  64
#define H_DIM 1024
#define D_HALF 64
#define W_WIN 129            // 2*D+1
#define DCH   64             // d-chunk for GEMM partial
#define NDC   (H_DIM / DCH)  // 16
#define NT    768            // fused kernel threads (24 warps)

// Scratch (allocation-free)
__device__ float g_dotp[NDC * B_SZ * H_DIM];   // [dc][b][h]  4 MB

// ---------------------------------------------------------------------------
// K1: partial GEMM  dotp[dc][b][h] = sum_{d in chunk dc} hidden[b][d]*Wp_w[h][d]
// fp32 on purpose: p feeds round() -> window center; precision is structural.
// ---------------------------------------------------------------------------
__global__ __launch_bounds__(256, 2)
void k_gemm_partial(const float* __restrict__ hidden,
                    const float* __restrict__ Wp_w) {
    const int h0 = blockIdx.x * 64;
    const int dc = blockIdx.y;
    const int d0 = dc * DCH;

    __shared__ float sh_h[64][65];   // [b][d] padded
    __shared__ float sh_w[DCH][65];  // [d][h] padded (transposed)

    const int tid  = threadIdx.x;
    const int lane = tid & 31;
    const int warp = tid >> 5;

    for (int idx = tid; idx < 64 * 16; idx += 256) {
        int b  = idx >> 4;
        int dq = (idx & 15) << 2;
        float4 v = *reinterpret_cast<const float4*>(&hidden[b * H_DIM + d0 + dq]);
        sh_h[b][dq + 0] = v.x; sh_h[b][dq + 1] = v.y;
        sh_h[b][dq + 2] = v.z; sh_h[b][dq + 3] = v.w;
    }
    for (int idx = tid; idx < 64 * 16; idx += 256) {
        int h  = idx >> 4;
        int dq = (idx & 15) << 2;
        float4 v = *reinterpret_cast<const float4*>(&Wp_w[(size_t)(h0 + h) * H_DIM + d0 + dq]);
        sh_w[dq + 0][h] = v.x; sh_w[dq + 1][h] = v.y;
        sh_w[dq + 2][h] = v.z; sh_w[dq + 3][h] = v.w;
    }
    __syncthreads();

    const int hl = lane & 15;
    const int bl = ((lane >> 4) << 2) + (warp << 3);

    float acc[4][4] = {};
#pragma unroll 16
    for (int d = 0; d < DCH; ++d) {
        float wv0 = sh_w[d][hl];
        float wv1 = sh_w[d][hl + 16];
        float wv2 = sh_w[d][hl + 32];
        float wv3 = sh_w[d][hl + 48];
        float hv0 = sh_h[bl + 0][d];
        float hv1 = sh_h[bl + 1][d];
        float hv2 = sh_h[bl + 2][d];
        float hv3 = sh_h[bl + 3][d];
        acc[0][0] += hv0 * wv0; acc[0][1] += hv0 * wv1; acc[0][2] += hv0 * wv2; acc[0][3] += hv0 * wv3;
        acc[1][0] += hv1 * wv0; acc[1][1] += hv1 * wv1; acc[1][2] += hv1 * wv2; acc[1][3] += hv1 * wv3;
        acc[2][0] += hv2 * wv0; acc[2][1] += hv2 * wv1; acc[2][2] += hv2 * wv2; acc[2][3] += hv2 * wv3;
        acc[3][0] += hv3 * wv0; acc[3][1] += hv3 * wv1; acc[3][2] += hv3 * wv2; acc[3][3] += hv3 * wv3;
    }

    float* outp = &g_dotp[(size_t)dc * (B_SZ * H_DIM)];
#pragma unroll
    for (int j = 0; j < 4; ++j) {
        int b = bl + j;
#pragma unroll
        for (int i = 0; i < 4; ++i)
            outp[b * H_DIM + h0 + hl + 16 * i] = acc[j][i];
    }
}

// ---------------------------------------------------------------------------
// K2 (fused, clustered): 2 CTAs per b (cluster), 128 blocks total -> ~full chip.
// Rank r handles half the w-range (scores) and half the h-range (context).
// Tiny cross-CTA state (p partial, scores) exchanged via DSMEM.
// ---------------------------------------------------------------------------
__global__ __launch_bounds__(NT, 1) __cluster_dims__(2, 1, 1)
void k_attn_fused(const float* __restrict__ hidden,
                  const float* __restrict__ enc,
                  const float* __restrict__ Wp_b,
                  const float* __restrict__ vp_w,
                  const float* __restrict__ vp_b,
                  float* __restrict__ d_out) {
    cg::cluster_group cluster = cg::this_cluster();

    const int b    = blockIdx.x >> 1;
    const int rank = blockIdx.x & 1;
    const int peer = rank ^ 1;
    const int tid  = threadIdx.x;
    const int lane = tid & 31;
    const int warp = tid >> 5;   // 0..23

    __shared__ __align__(16) float sh_hid[H_DIM];
    __shared__ float  s_scores[W_WIN];
    __shared__ float  s_attn[W_WIN];
    __shared__ float  s_red[256];
    __shared__ float  s_wred[24];
    __shared__ float  s_part;          // this rank's p partial
    __shared__ float4 s_ctx[5][128];   // context combine for segs 1..5
    __shared__ float  s_p;
    __shared__ int    s_c;

    // stage full hidden row (both ranks need all of it for scores)
    for (int i = tid; i < H_DIM; i += NT) sh_hid[i] = hidden[b * H_DIM + i];

    // ---- phase 1: p partial over this rank's h-half ----
    {
        float local = 0.f;
        for (int h = tid; h < 512; h += NT) {   // 512 of 768 threads active
            const int hh = rank * 512 + h;
            float pa[NDC];
#pragma unroll
            for (int dc = 0; dc < NDC; ++dc)
                pa[dc] = g_dotp[dc * (B_SZ * H_DIM) + b * H_DIM + hh];
            float s = Wp_b[hh];
#pragma unroll
            for (int dc = 0; dc < NDC; ++dc) s += pa[dc];
            local += vp_w[hh] * tanhf(s);
        }
#pragma unroll
        for (int off = 16; off > 0; off >>= 1)
            local += __shfl_down_sync(0xffffffffu, local, off);
        if (lane == 0) s_wred[warp] = local;
        __syncthreads();
        if (warp == 0) {
            float v = (lane < 24) ? s_wred[lane] : 0.f;
#pragma unroll
            for (int off = 16; off > 0; off >>= 1)
                v += __shfl_down_sync(0xffffffffu, v, off);
            if (lane == 0) s_part = v;
        }
    }
    cluster.sync();   // publish s_part to peer

    if (tid == 0) {
        const float* pp = (const float*)cluster.map_shared_rank((void*)&s_part, peer);
        float tot = s_part + *pp + vp_b[0];    // commutative add: identical in both ranks
        float p = (float)S_LEN / (1.f + expf(-tot));
        s_p = p;
        s_c = (int)rintf(p);                   // round-half-even == jnp.round
    }
    __syncthreads();
    const int   c = s_c;
    const float p = s_p;

    // ---- phase 2: scores over this rank's w-half, one warp per w, MLP=8 ----
    {
        const int wbeg = rank * 65;
        const int wend = rank ? W_WIN : 65;
        const float4* h4 = reinterpret_cast<const float4*>(sh_hid);
        for (int w = wbeg + warp; w < wend; w += 24) {
            const int s = c + w - D_HALF;
            float score = 0.f;
            if (s >= 0 && s < S_LEN) {
                const float4* e4 = reinterpret_cast<const float4*>(
                    enc + ((size_t)s * B_SZ + b) * H_DIM);
                float4 e[8];
#pragma unroll
                for (int k = 0; k < 8; ++k) e[k] = e4[k * 32 + lane];   // batched LDG.128
                float a0 = 0.f, a1 = 0.f, a2 = 0.f, a3 = 0.f;
#pragma unroll
                for (int k = 0; k < 8; ++k) {
                    float4 hh = h4[k * 32 + lane];
                    a0 += e[k].x * hh.x; a1 += e[k].y * hh.y;
                    a2 += e[k].z * hh.z; a3 += e[k].w * hh.w;
                }
                float v = (a0 + a1) + (a2 + a3);
#pragma unroll
                for (int off = 16; off > 0; off >>= 1)
                    v += __shfl_down_sync(0xffffffffu, v, off);
                score = v;
            }
            if (lane == 0) s_scores[w] = score;
        }
    }
    cluster.sync();   // publish this rank's score half

    // fetch peer's score half via DSMEM
    {
        const float* ps = (const float*)cluster.map_shared_rank((void*)s_scores, peer);
        const int plo = peer * 65;
        const int phi = peer ? W_WIN : 65;
        for (int i = plo + tid; i < phi; i += NT) s_scores[i] = ps[i];
    }
    __syncthreads();

    // ---- phase 3: softmax x gaussian (redundant in both ranks, identical) ----
    float sc = (tid < W_WIN) ? s_scores[tid] : -1e30f;
    if (tid < 256) s_red[tid] = sc;
    __syncthreads();
    for (int s2 = 128; s2 > 0; s2 >>= 1) {
        if (tid < s2) s_red[tid] = fmaxf(s_red[tid], s_red[tid + s2]);
        __syncthreads();
    }
    float mx = s_red[0];
    __syncthreads();
    float e = (tid < W_WIN) ? expf(sc - mx) : 0.f;
    if (tid < 256) s_red[tid] = e;
    __syncthreads();
    for (int s2 = 128; s2 > 0; s2 >>= 1) {
        if (tid < s2) s_red[tid] += s_red[tid + s2];
        __syncthreads();
    }
    float denom = s_red[0];
    if (tid < W_WIN) {
        float pos  = (float)(c + tid - D_HALF);
        float diff = pos - p;
        float val  = (e / denom) * expf(-diff * diff * (1.f / 2048.f)); // stddev=D/2=32
        s_attn[tid] = val;
        if (rank == 0) d_out[b * W_WIN + tid] = val;
    }
    __syncthreads();

    // ---- phase 4: context over this rank's h-half, 6 w-segments x 128 threads ----
    {
        const int lo = max(0, D_HALF - c);
        const int hi = min(W_WIN, S_LEN + D_HALF - c);
        const int seg  = tid >> 7;     // 0..5
        const int hidx = tid & 127;    // float4 index within 512-float half

        const float4* base = reinterpret_cast<const float4*>(
            enc + (size_t)b * H_DIM + rank * 512) + hidx;
        const size_t rs4 = (size_t)(B_SZ * H_DIM) / 4;

        float4 acc = make_float4(0.f, 0.f, 0.f, 0.f);
        int w = lo + seg;
        for (; w + 42 < hi; w += 48) {          // 8-deep batch at stride 6
            float4 ev[8];
            float  av[8];
#pragma unroll
            for (int j = 0; j < 8; ++j) {
                int ww = w + 6 * j;
                ev[j] = base[(size_t)(c + ww - D_HALF) * rs4];   // batched LDG.128
                av[j] = s_attn[ww];
            }
#pragma unroll
            for (int j = 0; j < 8; ++j) {
                acc.x += av[j] * ev[j].x; acc.y += av[j] * ev[j].y;
                acc.z += av[j] * ev[j].z; acc.w += av[j] * ev[j].w;
            }
        }
        for (; w < hi; w += 6) {
            float4 ev = base[(size_t)(c + w - D_HALF) * rs4];
            float  a  = s_attn[w];
            acc.x += a * ev.x; acc.y += a * ev.y;
            acc.z += a * ev.z; acc.w += a * ev.w;
        }

        if (seg > 0) s_ctx[seg - 1][hidx] = acc;
        __syncthreads();
        if (seg == 0) {
            float4 o = acc;
#pragma unroll
            for (int j = 0; j < 5; ++j) {
                float4 t = s_ctx[j][hidx];
                o.x += t.x; o.y += t.y; o.z += t.z; o.w += t.w;
            }
            reinterpret_cast<float4*>(
                d_out + B_SZ * W_WIN + b * H_DIM + rank * 512)[hidx] = o;
        }
    }

    cluster.sync();   // no CTA exits while peer may still touch its DSMEM
}

// ---------------------------------------------------------------------------
extern "C" void kernel_launch(void* const* d_in, const int* in_sizes, int n_in,
                              void* d_out, int out_size) {
    // metadata order: t, hidden, encoder_outputs, Wp_w, Wp_b, vp_w, vp_b
    const float* hidden = (const float*)d_in[1];
    const float* enc    = (const float*)d_in[2];
    const float* Wp_w   = (const float*)d_in[3];
    const float* Wp_b   = (const float*)d_in[4];
    const float* vp_w   = (const float*)d_in[5];
    const float* vp_b   = (const float*)d_in[6];
    float* out = (float*)d_out;

    k_gemm_partial<<<dim3(16, 16), 256>>>(hidden, Wp_w);
    k_attn_fused<<<B_SZ * 2, NT>>>(hidden, enc, Wp_b, vp_w, vp_b, out);
}